// round 11
// baseline (speedup 1.0000x reference)
#include <cuda_runtime.h>

// BezierToImageLayer — sparse Gaussian splat, round 11.
// R11 vs R10 (55.8us): FOUR curves per warp (quarter-warps of 8 lanes).
//  - lane owns one full row (residue mod 8) of its curve's 8x8 window = 4 float2
//    cells, committed in 4 residue-phases: phase p, quarter q -> residue (p+q)&3.
//    Within a phase quarters occupy distinct col-pair residues -> race-free;
//    cross-phase collisions ordered by program order + compiler fences.
//  - per-sample overhead (SHFL/F2I/row math) amortized over 4 curve-samples.
//  - NSPLIT=5 (32 curves/task -> 8/warp = 2 groups of 4). Grid 1280.
//  - lanes hold 4 sample points each (n = hl+8j); width-8 shuffle broadcast.

#define BDIM     128
#define NWARPS   4
#define NSPLIT   5
#define WPIX     60
#define AROWS    67                         // rows -3..63
#define STRIDE   68                         // bank-pair (2i+P) mod 16: 2-phase LDS.64
#define RPAD     3
#define CPAD     4
#define NSAMP    30
#define NCURVE   160
#define CPT      (NCURVE / NSPLIT)          // 32 curves per task
#define NGROUP   2                          // groups of 4 curves per warp
#define COPY_W   (AROWS * STRIDE)           // 4556 floats
#define ACC_WORDS (NWARPS * COPY_W)         // 18224 floats = 72896 B

#define NBATCH   256
#define IMG      (WPIX * WPIX)

__device__ float g_scratch[NBATCH * NSPLIT * IMG];   // 18.4 MB partials (L2-hot)
__device__ int   g_cnt[NBATCH];                      // zero-init; reset by last CTA

__device__ __forceinline__ float ex2f(float a) {
    float r; asm("ex2.approx.f32 %0, %1;" : "=f"(r) : "f"(a)); return r;
}

__global__ __launch_bounds__(BDIM, 3)
void bezier_splat_kernel(const float* __restrict__ x, float* __restrict__ out)
{
    extern __shared__ float acc[];   // [NWARPS][AROWS][STRIDE], per-warp private

    const int task = blockIdx.x;          // 0..1279
    const int b    = task / NSPLIT;
    const int part = task - b * NSPLIT;
    const int tid  = threadIdx.x;
    const int w    = tid >> 5;
    const int lane = tid & 31;

    // ---- zero private accumulators ----
    float4* az = (float4*)acc;
    for (int i = tid; i < ACC_WORDS / 4; i += BDIM)
        az[i] = make_float4(0.f, 0.f, 0.f, 0.f);
    __syncthreads();

    float* __restrict__ my = acc + w * COPY_W + RPAD * STRIDE + CPAD;

    const int qtr = lane >> 3;         // which curve of the group (0..3)
    const int hl  = lane & 7;
    const int rl3 = hl + 3;            // row residue (mod 8), pre-biased

    // ---- basis for this lane's 4 sample indices: n = hl + 8j ----
    float B0[4], B1[4], B2[4], B3[4];
    #pragma unroll
    for (int j = 0; j < 4; ++j) {
        const int nn = hl + 8 * j;                 // n>=30 never broadcast
        const float u  = (float)nn * (1.0f / (float)NSAMP);
        const float t  = 2.0f*u*u*u - 3.0f*u*u + 2.0f*u;
        const float t2 = t * t;
        const float t3 = t2 * t;
        const float tb = 1.0f - t;
        B0[j] = 60.0f  * t3;
        B1[j] = 180.0f * (t2 - t3);
        B2[j] = 180.0f * (t3 - 2.0f*t2 + t);
        B3[j] = 60.0f  * tb * tb * tb;
    }

    const float C2 = -2.0037431123457827f;   // -(5000/3600)*log2(e)
    const float K  = 1.4155363231368842f;    // sqrt(-C2)

    const float* __restrict__ xb = x + ((size_t)b * NCURVE + part * CPT) * 8;

    #pragma unroll
    for (int g = 0; g < NGROUP; ++g) {
        // warp w, group g, quarter qtr -> curve w + 4*qtr + 16*g (bijective over 0..31)
        const float* ct = xb + (w + 4 * qtr + 16 * g) * 8;   // uniform per quarter

        // this lane's 4 sample points on its quarter's curve (pixel units)
        float Xs[4], Ys[4];
        #pragma unroll
        for (int j = 0; j < 4; ++j) {
            Xs[j] = B0[j]*ct[0] + B1[j]*ct[2] + B2[j]*ct[4] + B3[j]*ct[6];
            Ys[j] = B0[j]*ct[1] + B1[j]*ct[3] + B2[j]*ct[5] + B3[j]*ct[7];
        }

        #pragma unroll
        for (int j = 0; j < 4; ++j) {
            const int SC = (j < 3) ? 8 : 6;              // 3*8 + 6 = 30 samples
            #pragma unroll
            for (int s = 0; s < SC; ++s) {
                // width-8 broadcast: each quarter gets ITS curve's sample hl==s
                const float Xp = __shfl_sync(0xffffffffu, Xs[j], s, 8);
                const float Yp = __shfl_sync(0xffffffffu, Ys[j], s, 8);

                const int mi = (int)Xp;                  // [0,59], trunc == floor
                const int mj = (int)Yp;

                const int i    = mi - 3 + ((rl3 - mi) & 7);  // this lane's row
                const int P0   = (mj - 3) >> 1;
                const int base = qtr - P0;

                const float dx = ((float)i - Xp) * K;
                const float nx = -(dx * dx);
                float* __restrict__ row = my + i * STRIDE;

                #pragma unroll
                for (int p = 0; p < 4; ++p) {
                    const int off = (base + p) & 3;       // phase-p residue for qtr
                    const int P   = P0 + off;

                    const float dy = ((float)(2 * P) - Yp) * K;
                    const float e  = fmaf(dy, -dy, nx);
                    const float td = fmaf(dy, -2.0f * K, C2);
                    const float g1 = ex2f(e);
                    const float g2 = ex2f(e + td);

                    float2* __restrict__ pp = (float2*)(row + 2 * P);
                    float2 v = *pp;
                    v.x += g1;
                    v.y += g2;
                    *pp = v;
                    // phase boundary: later-phase LDS must not hoist above this STS
                    asm volatile("" ::: "memory");
                }
            }
        }
    }
    __syncthreads();

    // ---- reduce 4 private copies -> scratch partial (float4) ----
    float4* __restrict__ sp4 = (float4*)(g_scratch + (size_t)task * IMG);
    const float* __restrict__ a0 = acc + RPAD * STRIDE + CPAD;
    for (int qd = tid; qd < IMG / 4; qd += BDIM) {        // 900 quads
        const int i = qd / (WPIX / 4);
        const int k = qd - i * (WPIX / 4);
        const int o = i * STRIDE + 4 * k;
        float4 s0 = *(const float4*)(a0 + o);
        #pragma unroll
        for (int ww = 1; ww < NWARPS; ++ww) {
            const float4 v = *(const float4*)(a0 + ww * COPY_W + o);
            s0.x += v.x; s0.y += v.y; s0.z += v.z; s0.w += v.w;
        }
        sp4[qd] = s0;
    }

    // ---- last task of this batch combines the 5 partials ----
    __threadfence();
    __syncthreads();
    __shared__ int s_last;
    if (tid == 0) {
        int old = atomicAdd(&g_cnt[b], 1);
        s_last = (old == NSPLIT - 1);
    }
    __syncthreads();
    if (s_last) {
        __threadfence();   // acquire: see all tasks' scratch writes
        const float4* __restrict__ base =
            (const float4*)(g_scratch + (size_t)b * NSPLIT * IMG);
        float4* __restrict__ ob = (float4*)(out + (size_t)b * IMG);
        for (int qd = tid; qd < IMG / 4; qd += BDIM) {
            float4 s0 = base[qd];
            #pragma unroll
            for (int k = 1; k < NSPLIT; ++k) {
                const float4 v = base[k * (IMG / 4) + qd];
                s0.x += v.x; s0.y += v.y; s0.z += v.z; s0.w += v.w;
            }
            s0.x = fminf(s0.x, 1.0f);
            s0.y = fminf(s0.y, 1.0f);
            s0.z = fminf(s0.z, 1.0f);
            s0.w = fminf(s0.w, 1.0f);
            ob[qd] = s0;
        }
        if (tid == 0) g_cnt[b] = 0;   // reset for next graph replay
    }
}

extern "C" void kernel_launch(void* const* d_in, const int* in_sizes, int n_in,
                              void* d_out, int out_size)
{
    (void)in_sizes; (void)n_in; (void)out_size;
    const float* x = (const float*)d_in[0];
    float* out     = (float*)d_out;

    cudaFuncSetAttribute(bezier_splat_kernel,
                         cudaFuncAttributeMaxDynamicSharedMemorySize,
                         ACC_WORDS * (int)sizeof(float));

    bezier_splat_kernel<<<NBATCH * NSPLIT, BDIM, ACC_WORDS * (int)sizeof(float)>>>(x, out);
}

// round 12
// speedup vs baseline: 1.1062x; 1.1062x over previous
#include <cuda_runtime.h>

// BezierToImageLayer — sparse Gaussian splat, round 12.
// R12 = R11 (4 curves/warp, 4-phase race-free commits) FIXED:
//  - s-loops rolled (body ~1.2KB, fits L0 I$; R11's full unroll hit ~60KB -> I$ stall)
//  - all 4 phases' exps/pointers hoisted ABOVE the fence-ordered RMW sequence
//    (R11 computed exps inside each phase -> chain 4x(compute+LDS) serial)
//  - phase p, quarter q commits col-pair residue (q+p) mod 4: distinct cells per
//    phase across quarters; same quarter = distinct rows; cross-phase by fences.

#define BDIM     128
#define NWARPS   4
#define NSPLIT   5
#define WPIX     60
#define AROWS    67                         // rows -3..63
#define STRIDE   68                         // bank-pair (2i+P) mod 16: 2-phase LDS.64
#define RPAD     3
#define CPAD     4
#define NSAMP    30
#define NCURVE   160
#define CPT      (NCURVE / NSPLIT)          // 32 curves per task
#define NGROUP   2                          // groups of 4 curves per warp
#define COPY_W   (AROWS * STRIDE)           // 4556 floats
#define ACC_WORDS (NWARPS * COPY_W)         // 18224 floats = 72896 B

#define NBATCH   256
#define IMG      (WPIX * WPIX)

__device__ float g_scratch[NBATCH * NSPLIT * IMG];   // 18.4 MB partials (L2-hot)
__device__ int   g_cnt[NBATCH];                      // zero-init; reset by last CTA

__device__ __forceinline__ float ex2f(float a) {
    float r; asm("ex2.approx.f32 %0, %1;" : "=f"(r) : "f"(a)); return r;
}

__global__ __launch_bounds__(BDIM, 3)
void bezier_splat_kernel(const float* __restrict__ x, float* __restrict__ out)
{
    extern __shared__ float acc[];   // [NWARPS][AROWS][STRIDE], per-warp private

    const int task = blockIdx.x;          // 0..1279
    const int b    = task / NSPLIT;
    const int part = task - b * NSPLIT;
    const int tid  = threadIdx.x;
    const int w    = tid >> 5;
    const int lane = tid & 31;

    // ---- zero private accumulators ----
    float4* az = (float4*)acc;
    for (int i = tid; i < ACC_WORDS / 4; i += BDIM)
        az[i] = make_float4(0.f, 0.f, 0.f, 0.f);
    __syncthreads();

    float* __restrict__ my = acc + w * COPY_W + RPAD * STRIDE + CPAD;

    const int qtr = lane >> 3;         // which curve of the group (0..3)
    const int hl  = lane & 7;
    const int rl3 = hl + 3;            // row residue (mod 8), pre-biased

    // ---- basis for this lane's 4 sample indices: n = hl + 8j ----
    float B0[4], B1[4], B2[4], B3[4];
    #pragma unroll
    for (int j = 0; j < 4; ++j) {
        const int nn = hl + 8 * j;                 // n>=30 never broadcast
        const float u  = (float)nn * (1.0f / (float)NSAMP);
        const float t  = 2.0f*u*u*u - 3.0f*u*u + 2.0f*u;
        const float t2 = t * t;
        const float t3 = t2 * t;
        const float tb = 1.0f - t;
        B0[j] = 60.0f  * t3;
        B1[j] = 180.0f * (t2 - t3);
        B2[j] = 180.0f * (t3 - 2.0f*t2 + t);
        B3[j] = 60.0f  * tb * tb * tb;
    }

    const float C2 = -2.0037431123457827f;   // -(5000/3600)*log2(e) = -K*K
    const float K  = 1.4155363231368842f;    // sqrt(-C2)

    const float* __restrict__ xb = x + ((size_t)b * NCURVE + part * CPT) * 8;

    for (int g = 0; g < NGROUP; ++g) {
        // warp w, group g, quarter qtr -> curve w + 4*qtr + 16*g (bijective 0..31)
        const float* ct = xb + (w + 4 * qtr + 16 * g) * 8;   // uniform per quarter

        // this lane's 4 sample points on its quarter's curve (pixel units)
        float Xs[4], Ys[4];
        #pragma unroll
        for (int j = 0; j < 4; ++j) {
            Xs[j] = B0[j]*ct[0] + B1[j]*ct[2] + B2[j]*ct[4] + B3[j]*ct[6];
            Ys[j] = B0[j]*ct[1] + B1[j]*ct[3] + B2[j]*ct[5] + B3[j]*ct[7];
        }

        #pragma unroll
        for (int j = 0; j < 4; ++j) {
            const int SC = (j < 3) ? 8 : 6;              // 3*8 + 6 = 30 samples
            for (int s = 0; s < SC; ++s) {               // ROLLED: ~1.2KB body
                // width-8 broadcast: each quarter gets ITS curve's sample s
                const float Xp = __shfl_sync(0xffffffffu, Xs[j], s, 8);
                const float Yp = __shfl_sync(0xffffffffu, Ys[j], s, 8);

                const int mi = (int)Xp;                  // [0,59], trunc == floor
                const int mj = (int)Yp;

                const int i    = mi - 3 + ((rl3 - mi) & 7);  // this lane's row
                const int P0   = (mj - 3) >> 1;
                const int base = qtr - P0;

                const float dx  = ((float)i - Xp) * K;
                const float nx  = -(dx * dx);
                const float dy0 = ((float)(2 * P0) - Yp) * K;
                float* __restrict__ row = my + i * STRIDE;

                // ---- hoisted compute stage: all 4 phases' g/ptr ----
                float  G1[4], G2[4];
                float2* PT[4];
                #pragma unroll
                for (int p = 0; p < 4; ++p) {
                    const int off = (base + p) & 3;       // phase-p residue (q+p mod 4)
                    const float dy = fmaf((float)off, 2.0f * K, dy0);
                    const float e  = fmaf(dy, -dy, nx);
                    const float td = fmaf(dy, -2.0f * K, C2);
                    G1[p] = ex2f(e);
                    G2[p] = ex2f(e + td);
                    PT[p] = (float2*)(row + 2 * (P0 + off));
                }

                // ---- fence-ordered RMW stage ----
                #pragma unroll
                for (int p = 0; p < 4; ++p) {
                    float2 v = *PT[p];
                    v.x += G1[p];
                    v.y += G2[p];
                    *PT[p] = v;
                    if (p < 3) asm volatile("" ::: "memory");
                }
            }
        }
    }
    __syncthreads();

    // ---- reduce 4 private copies -> scratch partial (float4) ----
    float4* __restrict__ sp4 = (float4*)(g_scratch + (size_t)task * IMG);
    const float* __restrict__ a0 = acc + RPAD * STRIDE + CPAD;
    for (int qd = tid; qd < IMG / 4; qd += BDIM) {        // 900 quads
        const int i = qd / (WPIX / 4);
        const int k = qd - i * (WPIX / 4);
        const int o = i * STRIDE + 4 * k;
        float4 s0 = *(const float4*)(a0 + o);
        #pragma unroll
        for (int ww = 1; ww < NWARPS; ++ww) {
            const float4 v = *(const float4*)(a0 + ww * COPY_W + o);
            s0.x += v.x; s0.y += v.y; s0.z += v.z; s0.w += v.w;
        }
        sp4[qd] = s0;
    }

    // ---- last task of this batch combines the 5 partials ----
    __threadfence();
    __syncthreads();
    __shared__ int s_last;
    if (tid == 0) {
        int old = atomicAdd(&g_cnt[b], 1);
        s_last = (old == NSPLIT - 1);
    }
    __syncthreads();
    if (s_last) {
        __threadfence();   // acquire: see all tasks' scratch writes
        const float4* __restrict__ base4 =
            (const float4*)(g_scratch + (size_t)b * NSPLIT * IMG);
        float4* __restrict__ ob = (float4*)(out + (size_t)b * IMG);
        for (int qd = tid; qd < IMG / 4; qd += BDIM) {
            float4 s0 = base4[qd];
            #pragma unroll
            for (int k = 1; k < NSPLIT; ++k) {
                const float4 v = base4[k * (IMG / 4) + qd];
                s0.x += v.x; s0.y += v.y; s0.z += v.z; s0.w += v.w;
            }
            s0.x = fminf(s0.x, 1.0f);
            s0.y = fminf(s0.y, 1.0f);
            s0.z = fminf(s0.z, 1.0f);
            s0.w = fminf(s0.w, 1.0f);
            ob[qd] = s0;
        }
        if (tid == 0) g_cnt[b] = 0;   // reset for next graph replay
    }
}

extern "C" void kernel_launch(void* const* d_in, const int* in_sizes, int n_in,
                              void* d_out, int out_size)
{
    (void)in_sizes; (void)n_in; (void)out_size;
    const float* x = (const float*)d_in[0];
    float* out     = (float*)d_out;

    cudaFuncSetAttribute(bezier_splat_kernel,
                         cudaFuncAttributeMaxDynamicSharedMemorySize,
                         ACC_WORDS * (int)sizeof(float));

    bezier_splat_kernel<<<NBATCH * NSPLIT, BDIM, ACC_WORDS * (int)sizeof(float)>>>(x, out);
}

// round 13
// speedup vs baseline: 1.1377x; 1.0284x over previous
#include <cuda_runtime.h>

// BezierToImageLayer — sparse Gaussian splat, round 13.
// R13 = R12 (4 curves/warp, 4-phase race-free commits, rolled loop) + INCREMENTAL
// GAUSSIAN: for fixed dx, g(y+1) = g(y)*r(y), r(y+1) = r(y)*const. Phase order
// visits col-pairs contiguously (+2 px steps, one -6 px wrap), so the within-pair
// ratio r chains with a constant multiply (RR2 / RW at the wrap).
// Compute stage: ~58 instrs, 5 MUFU (was ~75 / 8). All g/ptr hoisted above the
// fence-ordered RMW stage; registers constant-indexed.

#define BDIM     128
#define NWARPS   4
#define NSPLIT   5
#define WPIX     60
#define AROWS    67                         // rows -3..63
#define STRIDE   68                         // 2-phase LDS.64 bank behavior
#define RPAD     3
#define CPAD     4
#define NSAMP    30
#define NCURVE   160
#define CPT      (NCURVE / NSPLIT)          // 32 curves per task
#define NGROUP   2                          // groups of 4 curves per warp
#define COPY_W   (AROWS * STRIDE)           // 4556 floats
#define ACC_WORDS (NWARPS * COPY_W)         // 18224 floats = 72896 B

#define NBATCH   256
#define IMG      (WPIX * WPIX)

__device__ float g_scratch[NBATCH * NSPLIT * IMG];   // 18.4 MB partials (L2-hot)
__device__ int   g_cnt[NBATCH];                      // zero-init; reset by last CTA

__device__ __forceinline__ float ex2f(float a) {
    float r; asm("ex2.approx.f32 %0, %1;" : "=f"(r) : "f"(a)); return r;
}

__global__ __launch_bounds__(BDIM, 3)
void bezier_splat_kernel(const float* __restrict__ x, float* __restrict__ out)
{
    extern __shared__ float acc[];   // [NWARPS][AROWS][STRIDE], per-warp private

    const int task = blockIdx.x;          // 0..1279
    const int b    = task / NSPLIT;
    const int part = task - b * NSPLIT;
    const int tid  = threadIdx.x;
    const int w    = tid >> 5;
    const int lane = tid & 31;

    // ---- zero private accumulators ----
    float4* az = (float4*)acc;
    for (int i = tid; i < ACC_WORDS / 4; i += BDIM)
        az[i] = make_float4(0.f, 0.f, 0.f, 0.f);
    __syncthreads();

    float* __restrict__ my = acc + w * COPY_W + RPAD * STRIDE + CPAD;

    const int qtr = lane >> 3;         // which curve of the group (0..3)
    const int hl  = lane & 7;
    const int rl3 = hl + 3;            // row residue (mod 8), pre-biased

    // ---- basis for this lane's 4 sample indices: n = hl + 8j ----
    float B0[4], B1[4], B2[4], B3[4];
    #pragma unroll
    for (int j = 0; j < 4; ++j) {
        const int nn = hl + 8 * j;                 // n>=30 never broadcast
        const float u  = (float)nn * (1.0f / (float)NSAMP);
        const float t  = 2.0f*u*u*u - 3.0f*u*u + 2.0f*u;
        const float t2 = t * t;
        const float t3 = t2 * t;
        const float tb = 1.0f - t;
        B0[j] = 60.0f  * t3;
        B1[j] = 180.0f * (t2 - t3);
        B2[j] = 180.0f * (t3 - 2.0f*t2 + t);
        B3[j] = 60.0f  * tb * tb * tb;
    }

    const float C2  = -2.0037431123457827f;   // -(5000/3600)*log2(e) = -K*K
    const float K   = 1.4155363231368842f;    // sqrt(-C2)
    // ratio-chain constants: r(y) = ex2(C2*(2d+1)); r(d+2)/r(d)=ex2(4*C2),
    // r(d-6)/r(d)=ex2(-12*C2)
    const float RR2 = 0.0038573923003404524f; // 2^(4*C2)  = 2^-8.01497
    const float RW  = 17271447.0f;            // 2^(-12*C2)= 2^+24.0449

    const float* __restrict__ xb = x + ((size_t)b * NCURVE + part * CPT) * 8;

    for (int g = 0; g < NGROUP; ++g) {
        // warp w, group g, quarter qtr -> curve w + 4*qtr + 16*g (bijective 0..31)
        const float* ct = xb + (w + 4 * qtr + 16 * g) * 8;   // uniform per quarter

        // this lane's 4 sample points on its quarter's curve (pixel units)
        float Xs[4], Ys[4];
        #pragma unroll
        for (int j = 0; j < 4; ++j) {
            Xs[j] = B0[j]*ct[0] + B1[j]*ct[2] + B2[j]*ct[4] + B3[j]*ct[6];
            Ys[j] = B0[j]*ct[1] + B1[j]*ct[3] + B2[j]*ct[5] + B3[j]*ct[7];
        }

        #pragma unroll
        for (int j = 0; j < 4; ++j) {
            const int SC = (j < 3) ? 8 : 6;              // 3*8 + 6 = 30 samples
            for (int s = 0; s < SC; ++s) {               // rolled: small body
                // width-8 broadcast: each quarter gets ITS curve's sample s
                const float Xp = __shfl_sync(0xffffffffu, Xs[j], s, 8);
                const float Yp = __shfl_sync(0xffffffffu, Ys[j], s, 8);

                const int mi = (int)Xp;                  // [0,59], trunc == floor
                const int mj = (int)Yp;

                const int i    = mi - 3 + ((rl3 - mi) & 7);  // this lane's row
                const int P0   = (mj - 3) >> 1;
                const int base = (qtr - P0) & 3;

                const float dxK = ((float)i - Xp) * K;
                const float nx  = -(dxK * dxK);
                float* __restrict__ row = my + i * STRIDE;

                // ---- hoisted compute stage: chained g/r across the 4 phases ----
                int   P   = P0 + base;
                float dyK = ((float)(2 * P) - Yp) * K;
                float r   = ex2f(fmaf(dyK, -2.0f * K, C2));   // r at first cell

                float  G1[4], G2[4];
                float2* PT[4];
                #pragma unroll
                for (int p = 0; p < 4; ++p) {
                    G1[p] = ex2f(fmaf(dyK, -dyK, nx));        // gx*gy at col 2P
                    G2[p] = G1[p] * r;                        // col 2P+1 via ratio
                    PT[p] = (float2*)(row + 2 * P);
                    if (p < 3) {                              // advance to next pair
                        const bool wrap = (P - P0) == 3;      // off 3 -> 0
                        P   = wrap ? P0 : (P + 1);
                        dyK = dyK + (wrap ? (-6.0f * K) : (2.0f * K));
                        r   = r * (wrap ? RW : RR2);
                    }
                }

                // ---- fence-ordered RMW stage (race-free: residue (qtr+p) mod 4) ----
                #pragma unroll
                for (int p = 0; p < 4; ++p) {
                    float2 v = *PT[p];
                    v.x += G1[p];
                    v.y += G2[p];
                    *PT[p] = v;
                    if (p < 3) asm volatile("" ::: "memory");
                }
            }
        }
    }
    __syncthreads();

    // ---- reduce 4 private copies -> scratch partial (float4) ----
    float4* __restrict__ sp4 = (float4*)(g_scratch + (size_t)task * IMG);
    const float* __restrict__ a0 = acc + RPAD * STRIDE + CPAD;
    for (int qd = tid; qd < IMG / 4; qd += BDIM) {        // 900 quads
        const int i = qd / (WPIX / 4);
        const int k = qd - i * (WPIX / 4);
        const int o = i * STRIDE + 4 * k;
        float4 s0 = *(const float4*)(a0 + o);
        #pragma unroll
        for (int ww = 1; ww < NWARPS; ++ww) {
            const float4 v = *(const float4*)(a0 + ww * COPY_W + o);
            s0.x += v.x; s0.y += v.y; s0.z += v.z; s0.w += v.w;
        }
        sp4[qd] = s0;
    }

    // ---- last task of this batch combines the 5 partials ----
    __threadfence();
    __syncthreads();
    __shared__ int s_last;
    if (tid == 0) {
        int old = atomicAdd(&g_cnt[b], 1);
        s_last = (old == NSPLIT - 1);
    }
    __syncthreads();
    if (s_last) {
        __threadfence();   // acquire: see all tasks' scratch writes
        const float4* __restrict__ base4 =
            (const float4*)(g_scratch + (size_t)b * NSPLIT * IMG);
        float4* __restrict__ ob = (float4*)(out + (size_t)b * IMG);
        for (int qd = tid; qd < IMG / 4; qd += BDIM) {
            float4 s0 = base4[qd];
            #pragma unroll
            for (int k = 1; k < NSPLIT; ++k) {
                const float4 v = base4[k * (IMG / 4) + qd];
                s0.x += v.x; s0.y += v.y; s0.z += v.z; s0.w += v.w;
            }
            s0.x = fminf(s0.x, 1.0f);
            s0.y = fminf(s0.y, 1.0f);
            s0.z = fminf(s0.z, 1.0f);
            s0.w = fminf(s0.w, 1.0f);
            ob[qd] = s0;
        }
        if (tid == 0) g_cnt[b] = 0;   // reset for next graph replay
    }
}

extern "C" void kernel_launch(void* const* d_in, const int* in_sizes, int n_in,
                              void* d_out, int out_size)
{
    (void)in_sizes; (void)n_in; (void)out_size;
    const float* x = (const float*)d_in[0];
    float* out     = (float*)d_out;

    cudaFuncSetAttribute(bezier_splat_kernel,
                         cudaFuncAttributeMaxDynamicSharedMemorySize,
                         ACC_WORDS * (int)sizeof(float));

    bezier_splat_kernel<<<NBATCH * NSPLIT, BDIM, ACC_WORDS * (int)sizeof(float)>>>(x, out);
}